// round 15
// baseline (speedup 1.0000x reference)
#include <cuda_runtime.h>
#include <cuda_fp16.h>

#define BB    16
#define NN    65536
#define CC    256
#define DINN  16
#define DOUTT 16

__device__ __align__(16) __half g_s[DINN * BB * CC];      // s: [i][b][k], fp16
__device__ __align__(16) float  g_wdt[CC * DOUTT * DINN]; // w_diag: [c][o][i]
__device__ __align__(16) float  g_off[BB * CC * DOUTT];   // off: [b][c][o]

__device__ __forceinline__ float4 shfl_xor_f4(float4 v, int m) {
    v.x = __shfl_xor_sync(0xffffffffu, v.x, m);
    v.y = __shfl_xor_sync(0xffffffffu, v.y, m);
    v.z = __shfl_xor_sync(0xffffffffu, v.z, m);
    v.w = __shfl_xor_sync(0xffffffffu, v.w, m);
    return v;
}
__device__ __forceinline__ float dot4(float4 a, float4 b) {
    return a.x*b.x + a.y*b.y + a.z*b.z + a.w*b.w;
}
__device__ __forceinline__ void mma16816(float& d0, float& d1, float& d2, float& d3,
                                         unsigned a0, unsigned a1, unsigned a2, unsigned a3,
                                         unsigned b0, unsigned b1) {
    asm volatile(
        "mma.sync.aligned.m16n8k16.row.col.f32.f16.f16.f32 "
        "{%0,%1,%2,%3}, {%4,%5,%6,%7}, {%8,%9}, {%0,%1,%2,%3};\n"
        : "+f"(d0), "+f"(d1), "+f"(d2), "+f"(d3)
        : "r"(a0), "r"(a1), "r"(a2), "r"(a3), "r"(b0), "r"(b1));
}

// ---------------------------------------------------------------------------
// kT: transpose w_diag [o][i][c] -> [c][o*16+i]; zero g_off for kB atomics.
// ---------------------------------------------------------------------------
__global__ __launch_bounds__(256) void kT(const float* __restrict__ wdiag) {
    int idx = blockIdx.x * 256 + threadIdx.x;      // 65536 total
    int c  = idx & 255;
    int oi = idx >> 8;
    g_wdt[c * 256 + oi] = wdiag[idx];
    g_off[idx] = 0.f;
}

// ---------------------------------------------------------------------------
// kA: s[i][b][c] = sum_r x[b, pid[c*256+r], i]   (R6 body; c0 = c-offset)
// ---------------------------------------------------------------------------
__global__ __launch_bounds__(256) void kA(const float* __restrict__ x,
                                          const int* __restrict__ pid,
                                          int c0) {
    int c = blockIdx.x + c0, b = blockIdx.y;
    __shared__ int ids[256];
    __shared__ float4 red[32];
    int t = threadIdx.x;
    int q = t & 3, g = t >> 2;
    int warp = t >> 5, lane = t & 31;
    ids[t] = pid[c * 256 + t];
    __syncthreads();

    const float* xb = x + (size_t)b * NN * DINN;
    float4 acc = make_float4(0.f, 0.f, 0.f, 0.f);
#pragma unroll
    for (int j = 0; j < 4; j++) {
        int n = ids[g + 64 * j];
        float4 v = ((const float4*)(xb + (size_t)n * DINN))[q];
        acc.x += v.x; acc.y += v.y; acc.z += v.z; acc.w += v.w;
    }
#pragma unroll
    for (int m = 4; m < 32; m <<= 1) {
        float4 o = shfl_xor_f4(acc, m);
        acc.x += o.x; acc.y += o.y; acc.z += o.z; acc.w += o.w;
    }
    if (lane < 4) red[warp * 4 + lane] = acc;
    __syncthreads();
    if (t < 32) {
        float4 v = red[t];
#pragma unroll
        for (int m = 4; m < 32; m <<= 1) {
            float4 o = shfl_xor_f4(v, m);
            v.x += o.x; v.y += o.y; v.z += o.z; v.w += o.w;
        }
        if (t < 4) {
            int i0 = 4 * t;
            g_s[((i0 + 0) * BB + b) * CC + c] = __float2half(v.x);
            g_s[((i0 + 1) * BB + b) * CC + c] = __float2half(v.y);
            g_s[((i0 + 2) * BB + b) * CC + c] = __float2half(v.z);
            g_s[((i0 + 3) * BB + b) * CC + c] = __float2half(v.w);
        }
    }
}

// ---------------------------------------------------------------------------
// kB (R14 tensor-core k-split body; y passed as arg): block (c) owns
// k in [128y, 128y+128). f32 accum; halves combined via atomicAdd (2 commuting
// adds per cell -> deterministic).
// ---------------------------------------------------------------------------
__global__ __launch_bounds__(256) void kB(const float* __restrict__ woff, int y) {
    int c    = blockIdx.x;
    int t    = threadIdx.x;
    int w    = t >> 5;
    int lane = t & 31;
    int r    = lane >> 2;          // 0..7
    int cp   = (lane & 3) * 2;     // 0,2,4,6
    int kb   = w * 16 + cp;        // within 128-wide window

    __shared__ __align__(16) __half sh_s[16 * 128];   // [b][kk]  4 KB
    __shared__ __align__(16) __half sh_w[16 * 128];   // [o][kk]  4 KB
    __shared__ __align__(16) float  dred[8 * 256];    // [w][b*16+o] 8 KB

    int sb_b  = t >> 4;
    int sb_k4 = t & 15;
    int wo[2], wk4[2];
#pragma unroll
    for (int rr = 0; rr < 2; rr++) {
        int F = t + 256 * rr;
        wo[rr]  = F >> 5;
        wk4[rr] = F & 31;
    }

    const uint4* gs4 = (const uint4*)g_s;
    float4 wbuf[2];
    uint4  sbuf;

#pragma unroll
    for (int rr = 0; rr < 2; rr++)
        wbuf[rr] = __ldg((const float4*)(woff + (((size_t)wo[rr] * 16 + 0) * CC + c) * CC + y * 128) + wk4[rr]);
    sbuf = gs4[sb_b * 32 + y * 16 + sb_k4];

    float d0[4] = {0.f, 0.f, 0.f, 0.f};
    float d1[4] = {0.f, 0.f, 0.f, 0.f};

    for (int i = 0; i < 16; i++) {
#pragma unroll
        for (int rr = 0; rr < 2; rr++) {
            __half2 h0 = __floats2half2_rn(wbuf[rr].x, wbuf[rr].y);
            __half2 h1 = __floats2half2_rn(wbuf[rr].z, wbuf[rr].w);
            *(uint2*)&sh_w[wo[rr] * 128 + wk4[rr] * 4] =
                make_uint2(*(unsigned*)&h0, *(unsigned*)&h1);
        }
        ((uint4*)sh_s)[t] = sbuf;
        __syncthreads();

        if (i < 15) {
#pragma unroll
            for (int rr = 0; rr < 2; rr++)
                wbuf[rr] = __ldg((const float4*)(woff + (((size_t)wo[rr] * 16 + (i + 1)) * CC + c) * CC + y * 128) + wk4[rr]);
            sbuf = gs4[(i + 1) * 512 + sb_b * 32 + y * 16 + sb_k4];
        }

        unsigned a0 = *(const unsigned*)&sh_s[r * 128 + kb];
        unsigned a1 = *(const unsigned*)&sh_s[(r + 8) * 128 + kb];
        unsigned a2 = *(const unsigned*)&sh_s[r * 128 + kb + 8];
        unsigned a3 = *(const unsigned*)&sh_s[(r + 8) * 128 + kb + 8];
        unsigned b00 = *(const unsigned*)&sh_w[r * 128 + kb];
        unsigned b01 = *(const unsigned*)&sh_w[r * 128 + kb + 8];
        unsigned b10 = *(const unsigned*)&sh_w[(8 + r) * 128 + kb];
        unsigned b11 = *(const unsigned*)&sh_w[(8 + r) * 128 + kb + 8];
        mma16816(d0[0], d0[1], d0[2], d0[3], a0, a1, a2, a3, b00, b01);
        mma16816(d1[0], d1[1], d1[2], d1[3], a0, a1, a2, a3, b10, b11);
        __syncthreads();
    }

    *(float2*)&dred[w * 256 + r * 16 + cp]            = make_float2(d0[0], d0[1]);
    *(float2*)&dred[w * 256 + (r + 8) * 16 + cp]      = make_float2(d0[2], d0[3]);
    *(float2*)&dred[w * 256 + r * 16 + 8 + cp]        = make_float2(d1[0], d1[1]);
    *(float2*)&dred[w * 256 + (r + 8) * 16 + 8 + cp]  = make_float2(d1[2], d1[3]);
    __syncthreads();

    float sum = 0.f;
#pragma unroll
    for (int ww = 0; ww < 8; ww++) sum += dred[ww * 256 + t];
    int b = t >> 4, o = t & 15;
    atomicAdd(&g_off[((size_t)b * CC + c) * DOUTT + o], sum * (1.0f / (float)NN));
}

// ---------------------------------------------------------------------------
// kC (R6 exact, measured ~32us stable)
// ---------------------------------------------------------------------------
__global__ __launch_bounds__(256, 3) void kC(const float* __restrict__ x,
                                             const int* __restrict__ pid,
                                             const float* __restrict__ b1,
                                             float* __restrict__ out) {
    int c = blockIdx.x, b = blockIdx.y;
    int t = threadIdx.x;
    int q = t & 3, g = t >> 2;

    const int* pc = pid + c * 256;
    int ns[4];
    ns[0] = __ldg(pc + g);
    ns[1] = __ldg(pc + g + 64);
    ns[2] = __ldg(pc + g + 128);
    ns[3] = __ldg(pc + g + 192);

    float4 wreg[4][4];
    float  bs[4];
    const float* wc = g_wdt + c * 256;
#pragma unroll
    for (int oo = 0; oo < 4; oo++) {
        int o = 4 * q + oo;
        bs[oo] = __ldg(&g_off[((size_t)b * CC + c) * DOUTT + o]) + __ldg(b1 + o);
#pragma unroll
        for (int p = 0; p < 4; p++)
            wreg[oo][p] = *(const float4*)(wc + o * 16 + 4 * (q ^ p));
    }

    const float* xb = x + (size_t)b * NN * DINN;
    float* ob = out + (size_t)b * NN * DOUTT;

#pragma unroll
    for (int j = 0; j < 4; j++) {
        int n = ns[j];
        float4 X0 = ((const float4*)(xb + (size_t)n * DINN))[q];
        float4 X1 = shfl_xor_f4(X0, 1);
        float4 X2 = shfl_xor_f4(X0, 2);
        float4 X3 = shfl_xor_f4(X0, 3);

        float r0 = bs[0], r1 = bs[1], r2 = bs[2], r3 = bs[3];
        r0 += dot4(wreg[0][0], X0) + dot4(wreg[0][1], X1) + dot4(wreg[0][2], X2) + dot4(wreg[0][3], X3);
        r1 += dot4(wreg[1][0], X0) + dot4(wreg[1][1], X1) + dot4(wreg[1][2], X2) + dot4(wreg[1][3], X3);
        r2 += dot4(wreg[2][0], X0) + dot4(wreg[2][1], X1) + dot4(wreg[2][2], X2) + dot4(wreg[2][3], X3);
        r3 += dot4(wreg[3][0], X0) + dot4(wreg[3][1], X1) + dot4(wreg[3][2], X2) + dot4(wreg[3][3], X3);

        ((float4*)(ob + (size_t)n * DOUTT))[q] = make_float4(r0, r1, r2, r3);
    }
}

// ---------------------------------------------------------------------------
// Launch: two-stream pipeline.
//   stream0: kT -> kA(c<128) -[e1]-> kA(c>=128) -[e2]-> ... -> kC
//   s2:      wait(e1) -> kB(y=0) ; wait(e2) -> kB(y=1) -[eB]-> join stream0
// kB(y) needs only s columns k in [128y,128y+128) == kA c-half y, plus kT.
// Stream/events created fresh per call (kernel_launch runs exactly twice:
// correctness + capture) — no static state, no device allocation.
// ---------------------------------------------------------------------------
extern "C" void kernel_launch(void* const* d_in, const int* in_sizes, int n_in,
                              void* d_out, int out_size) {
    const float* x     = (const float*)d_in[0];
    const float* wdiag = (const float*)d_in[1];
    const float* woff  = (const float*)d_in[2];
    const float* b1    = (const float*)d_in[3];
    const int*   pid   = (const int*)d_in[4];
    float* out = (float*)d_out;

    cudaStream_t s2;
    cudaStreamCreateWithFlags(&s2, cudaStreamNonBlocking);
    cudaEvent_t e1, e2, eB;
    cudaEventCreateWithFlags(&e1, cudaEventDisableTiming);
    cudaEventCreateWithFlags(&e2, cudaEventDisableTiming);
    cudaEventCreateWithFlags(&eB, cudaEventDisableTiming);

    kT<<<256, 256>>>(wdiag);
    kA<<<dim3(128, BB), 256>>>(x, pid, 0);
    cudaEventRecord(e1, 0);
    kA<<<dim3(128, BB), 256>>>(x, pid, 128);
    cudaEventRecord(e2, 0);

    cudaStreamWaitEvent(s2, e1, 0);
    kB<<<CC, 256, 0, s2>>>(woff, 0);
    cudaStreamWaitEvent(s2, e2, 0);
    kB<<<CC, 256, 0, s2>>>(woff, 1);
    cudaEventRecord(eB, s2);

    cudaStreamWaitEvent(0, eB, 0);
    kC<<<dim3(CC, BB), 256>>>(x, pid, b1, out);
}

// round 16
// speedup vs baseline: 1.4848x; 1.4848x over previous
#include <cuda_runtime.h>
#include <cuda_fp16.h>

#define BB    16
#define NN    65536
#define CC    256
#define DINN  16
#define DOUTT 16

__device__ __align__(16) __half g_s[DINN * BB * CC];      // s: [i][b][k], fp16
__device__ __align__(16) float  g_wdt[CC * DOUTT * DINN]; // w_diag: [c][o][i]
__device__ __align__(16) float  g_off[BB * CC * DOUTT];   // off: [b][c][o]

__device__ __forceinline__ float4 shfl_xor_f4(float4 v, int m) {
    v.x = __shfl_xor_sync(0xffffffffu, v.x, m);
    v.y = __shfl_xor_sync(0xffffffffu, v.y, m);
    v.z = __shfl_xor_sync(0xffffffffu, v.z, m);
    v.w = __shfl_xor_sync(0xffffffffu, v.w, m);
    return v;
}
__device__ __forceinline__ float dot4(float4 a, float4 b) {
    return a.x*b.x + a.y*b.y + a.z*b.z + a.w*b.w;
}
__device__ __forceinline__ void mma16816(float& d0, float& d1, float& d2, float& d3,
                                         unsigned a0, unsigned a1, unsigned a2, unsigned a3,
                                         unsigned b0, unsigned b1) {
    asm volatile(
        "mma.sync.aligned.m16n8k16.row.col.f32.f16.f16.f32 "
        "{%0,%1,%2,%3}, {%4,%5,%6,%7}, {%8,%9}, {%0,%1,%2,%3};\n"
        : "+f"(d0), "+f"(d1), "+f"(d2), "+f"(d3)
        : "r"(a0), "r"(a1), "r"(a2), "r"(a3), "r"(b0), "r"(b1));
}

// ---------------------------------------------------------------------------
// kT: transpose w_diag [o][i][c] -> [c][o*16+i]; zero g_off for kB atomics.
// ---------------------------------------------------------------------------
__global__ __launch_bounds__(256) void kT(const float* __restrict__ wdiag) {
    int idx = blockIdx.x * 256 + threadIdx.x;      // 65536 total
    int c  = idx & 255;
    int oi = idx >> 8;
    g_wdt[c * 256 + oi] = wdiag[idx];
    g_off[idx] = 0.f;
}

// ---------------------------------------------------------------------------
// kA: s[i][b][c] = sum_r x[b, pid[c*256+r], i]   (R6 exact)
// ---------------------------------------------------------------------------
__global__ __launch_bounds__(256) void kA(const float* __restrict__ x,
                                          const int* __restrict__ pid) {
    int c = blockIdx.x, b = blockIdx.y;
    __shared__ int ids[256];
    __shared__ float4 red[32];
    int t = threadIdx.x;
    int q = t & 3, g = t >> 2;
    int warp = t >> 5, lane = t & 31;
    ids[t] = pid[c * 256 + t];
    __syncthreads();

    const float* xb = x + (size_t)b * NN * DINN;
    float4 acc = make_float4(0.f, 0.f, 0.f, 0.f);
#pragma unroll
    for (int j = 0; j < 4; j++) {
        int n = ids[g + 64 * j];
        float4 v = ((const float4*)(xb + (size_t)n * DINN))[q];
        acc.x += v.x; acc.y += v.y; acc.z += v.z; acc.w += v.w;
    }
#pragma unroll
    for (int m = 4; m < 32; m <<= 1) {
        float4 o = shfl_xor_f4(acc, m);
        acc.x += o.x; acc.y += o.y; acc.z += o.z; acc.w += o.w;
    }
    if (lane < 4) red[warp * 4 + lane] = acc;
    __syncthreads();
    if (t < 32) {
        float4 v = red[t];
#pragma unroll
        for (int m = 4; m < 32; m <<= 1) {
            float4 o = shfl_xor_f4(v, m);
            v.x += o.x; v.y += o.y; v.z += o.z; v.w += o.w;
        }
        if (t < 4) {
            int i0 = 4 * t;
            g_s[((i0 + 0) * BB + b) * CC + c] = __float2half(v.x);
            g_s[((i0 + 1) * BB + b) * CC + c] = __float2half(v.y);
            g_s[((i0 + 2) * BB + b) * CC + c] = __float2half(v.z);
            g_s[((i0 + 3) * BB + b) * CC + c] = __float2half(v.w);
        }
    }
}

// ---------------------------------------------------------------------------
// kB (tensor-core, 4-way partition): grid (C, 4); block (c, yz):
//   ky = yz & 1  -> k in [128ky, 128ky+128)
//   iz = yz >> 1 -> i in [8iz, 8iz+8)
// True partition of w_off and s (no duplicated DRAM traffic). 8 barrier
// rounds per block; 1024 blocks (~7/SM) overlap the LDG latency chains.
// f32 accum; 4 commuting atomicAdds per off-cell (g_off zeroed in kT).
// ---------------------------------------------------------------------------
__global__ __launch_bounds__(256) void kB(const float* __restrict__ woff) {
    int c    = blockIdx.x;
    int ky   = blockIdx.y & 1;
    int iz   = blockIdx.y >> 1;
    int i0   = iz * 8;
    int t    = threadIdx.x;
    int w    = t >> 5;
    int lane = t & 31;
    int r    = lane >> 2;          // 0..7
    int cp   = (lane & 3) * 2;     // 0,2,4,6
    int kb   = w * 16 + cp;        // within 128-wide window

    __shared__ __align__(16) __half sh_s[16 * 128];   // [b][kk]  4 KB
    __shared__ __align__(16) __half sh_w[16 * 128];   // [o][kk]  4 KB
    __shared__ __align__(16) float  dred[8 * 256];    // [w][b*16+o] 8 KB

    int sb_b  = t >> 4;            // b
    int sb_k4 = t & 15;            // uint4 idx within 128-k window
    int wo[2], wk4[2];
#pragma unroll
    for (int rr = 0; rr < 2; rr++) {
        int F = t + 256 * rr;
        wo[rr]  = F >> 5;
        wk4[rr] = F & 31;
    }

    const uint4* gs4 = (const uint4*)g_s;
    float4 wbuf[2];
    uint4  sbuf;

    // preload slice i0
#pragma unroll
    for (int rr = 0; rr < 2; rr++)
        wbuf[rr] = __ldg((const float4*)(woff + (((size_t)wo[rr] * 16 + i0) * CC + c) * CC + ky * 128) + wk4[rr]);
    sbuf = gs4[i0 * 512 + sb_b * 32 + ky * 16 + sb_k4];

    float d0[4] = {0.f, 0.f, 0.f, 0.f};
    float d1[4] = {0.f, 0.f, 0.f, 0.f};

    for (int ii = 0; ii < 8; ii++) {
        int i = i0 + ii;
        // store staged slice i
#pragma unroll
        for (int rr = 0; rr < 2; rr++) {
            __half2 h0 = __floats2half2_rn(wbuf[rr].x, wbuf[rr].y);
            __half2 h1 = __floats2half2_rn(wbuf[rr].z, wbuf[rr].w);
            *(uint2*)&sh_w[wo[rr] * 128 + wk4[rr] * 4] =
                make_uint2(*(unsigned*)&h0, *(unsigned*)&h1);
        }
        ((uint4*)sh_s)[t] = sbuf;
        __syncthreads();

        // prefetch slice i+1
        if (ii < 7) {
#pragma unroll
            for (int rr = 0; rr < 2; rr++)
                wbuf[rr] = __ldg((const float4*)(woff + (((size_t)wo[rr] * 16 + (i + 1)) * CC + c) * CC + ky * 128) + wk4[rr]);
            sbuf = gs4[(i + 1) * 512 + sb_b * 32 + ky * 16 + sb_k4];
        }

        unsigned a0 = *(const unsigned*)&sh_s[r * 128 + kb];
        unsigned a1 = *(const unsigned*)&sh_s[(r + 8) * 128 + kb];
        unsigned a2 = *(const unsigned*)&sh_s[r * 128 + kb + 8];
        unsigned a3 = *(const unsigned*)&sh_s[(r + 8) * 128 + kb + 8];
        unsigned b00 = *(const unsigned*)&sh_w[r * 128 + kb];
        unsigned b01 = *(const unsigned*)&sh_w[r * 128 + kb + 8];
        unsigned b10 = *(const unsigned*)&sh_w[(8 + r) * 128 + kb];
        unsigned b11 = *(const unsigned*)&sh_w[(8 + r) * 128 + kb + 8];
        mma16816(d0[0], d0[1], d0[2], d0[3], a0, a1, a2, a3, b00, b01);
        mma16816(d1[0], d1[1], d1[2], d1[3], a0, a1, a2, a3, b10, b11);
        __syncthreads();
    }

    // write warp partials: D[b][o]
    *(float2*)&dred[w * 256 + r * 16 + cp]            = make_float2(d0[0], d0[1]);
    *(float2*)&dred[w * 256 + (r + 8) * 16 + cp]      = make_float2(d0[2], d0[3]);
    *(float2*)&dred[w * 256 + r * 16 + 8 + cp]        = make_float2(d1[0], d1[1]);
    *(float2*)&dred[w * 256 + (r + 8) * 16 + 8 + cp]  = make_float2(d1[2], d1[3]);
    __syncthreads();

    float sum = 0.f;
#pragma unroll
    for (int ww = 0; ww < 8; ww++) sum += dred[ww * 256 + t];
    int b = t >> 4, o = t & 15;
    atomicAdd(&g_off[((size_t)b * CC + c) * DOUTT + o], sum * (1.0f / (float)NN));
}

// ---------------------------------------------------------------------------
// kC (R6 exact, measured ~32us stable)
// ---------------------------------------------------------------------------
__global__ __launch_bounds__(256, 3) void kC(const float* __restrict__ x,
                                             const int* __restrict__ pid,
                                             const float* __restrict__ b1,
                                             float* __restrict__ out) {
    int c = blockIdx.x, b = blockIdx.y;
    int t = threadIdx.x;
    int q = t & 3, g = t >> 2;

    const int* pc = pid + c * 256;
    int ns[4];
    ns[0] = __ldg(pc + g);
    ns[1] = __ldg(pc + g + 64);
    ns[2] = __ldg(pc + g + 128);
    ns[3] = __ldg(pc + g + 192);

    float4 wreg[4][4];
    float  bs[4];
    const float* wc = g_wdt + c * 256;
#pragma unroll
    for (int oo = 0; oo < 4; oo++) {
        int o = 4 * q + oo;
        bs[oo] = __ldg(&g_off[((size_t)b * CC + c) * DOUTT + o]) + __ldg(b1 + o);
#pragma unroll
        for (int p = 0; p < 4; p++)
            wreg[oo][p] = *(const float4*)(wc + o * 16 + 4 * (q ^ p));
    }

    const float* xb = x + (size_t)b * NN * DINN;
    float* ob = out + (size_t)b * NN * DOUTT;

#pragma unroll
    for (int j = 0; j < 4; j++) {
        int n = ns[j];
        float4 X0 = ((const float4*)(xb + (size_t)n * DINN))[q];
        float4 X1 = shfl_xor_f4(X0, 1);
        float4 X2 = shfl_xor_f4(X0, 2);
        float4 X3 = shfl_xor_f4(X0, 3);

        float r0 = bs[0], r1 = bs[1], r2 = bs[2], r3 = bs[3];
        r0 += dot4(wreg[0][0], X0) + dot4(wreg[0][1], X1) + dot4(wreg[0][2], X2) + dot4(wreg[0][3], X3);
        r1 += dot4(wreg[1][0], X0) + dot4(wreg[1][1], X1) + dot4(wreg[1][2], X2) + dot4(wreg[1][3], X3);
        r2 += dot4(wreg[2][0], X0) + dot4(wreg[2][1], X1) + dot4(wreg[2][2], X2) + dot4(wreg[2][3], X3);
        r3 += dot4(wreg[3][0], X0) + dot4(wreg[3][1], X1) + dot4(wreg[3][2], X2) + dot4(wreg[3][3], X3);

        ((float4*)(ob + (size_t)n * DOUTT))[q] = make_float4(r0, r1, r2, r3);
    }
}

extern "C" void kernel_launch(void* const* d_in, const int* in_sizes, int n_in,
                              void* d_out, int out_size) {
    const float* x     = (const float*)d_in[0];
    const float* wdiag = (const float*)d_in[1];
    const float* woff  = (const float*)d_in[2];
    const float* b1    = (const float*)d_in[3];
    const int*   pid   = (const int*)d_in[4];
    float* out = (float*)d_out;

    kT<<<256, 256>>>(wdiag);
    kA<<<dim3(CC, BB), 256>>>(x, pid);
    kB<<<dim3(CC, 4), 256>>>(woff);
    kC<<<dim3(CC, BB), 256>>>(x, pid, b1, out);
}